// round 14
// baseline (speedup 1.0000x reference)
#include <cuda_runtime.h>
#include <cstdint>

// Block-diagonal grouped conv2d: 64 groups, 4 in-ch -> 4 out-ch per group, 3x3, pad 1.
// x:   (32, 256, 128, 128) fp32, channel index = ci*64 + head
// w:   (64, 4, 4, 3, 3)          w[head][co][ci][ky][kx]
// b:   (64, 4)
// out: (32, 256, 128, 128) fp32, channel index = co*64 + head
//
// v14 = v12 (128-thr CTAs, TY=8, cp.async staging, 2-row weight-amortized
//       co-pair f32x2 core) with __launch_bounds__(128,9): 56-reg target,
//       9 phase-staggered CTAs/SM (36 warps).

#define TY 8
#define SROWS (TY + 2)               // 10
#define SROW_P 132                   // row stride (floats); only 128 used
#define PLANE_P (SROWS * SROW_P)     // 1320
#define S_IN_FLOATS (4 * PLANE_P)    // 5280
#define THREADS 128
#define H 128
#define W 128
#define PLANE (H * W)
// s_in + 72 weight u64 + 2 bias u64
#define SMEM_BYTES (S_IN_FLOATS * 4 + 74 * 8)

typedef unsigned long long u64;

__device__ __forceinline__ u64 pk(float lo, float hi) {
    u64 r; asm("mov.b64 %0, {%1, %2};" : "=l"(r) : "f"(lo), "f"(hi)); return r;
}
__device__ __forceinline__ void upk(u64 v, float &lo, float &hi) {
    asm("mov.b64 {%0, %1}, %2;" : "=f"(lo), "=f"(hi) : "l"(v));
}
// d += a*b  (packed 2x fp32)
__device__ __forceinline__ void ffma2(u64 &d, u64 a, u64 b) {
    asm("fma.rn.f32x2 %0, %1, %2, %0;" : "+l"(d) : "l"(a), "l"(b));
}
__device__ __forceinline__ void cpasync16(uint32_t saddr, const float* g, bool pred) {
    int sz = pred ? 16 : 0;
    asm volatile("cp.async.cg.shared.global [%0], [%1], 16, %2;\n"
                 :: "r"(saddr), "l"(g), "r"(sz));
}

__global__ __launch_bounds__(THREADS, 9)
void bdconv_kernel(const float* __restrict__ x, const float* __restrict__ w,
                   const float* __restrict__ bias, float* __restrict__ out) {
    extern __shared__ __align__(16) float smem[];
    float* s_in = smem;                          // [ci][r][col], row-major
    u64*   s_w  = (u64*)(smem + S_IN_FLOATS);    // [ci][ky][kx][cp] co-pair
    u64*   s_b  = s_w + 72;                      // [cp]

    const int blk  = blockIdx.x;
    const int tile = blk & 15;          // 16 row-tiles of 8
    const int head = (blk >> 4) & 63;
    const int b    = blk >> 10;
    const int y0   = tile * TY;
    const int tid  = threadIdx.x;
    const int wrp  = tid >> 5;
    const int lane = tid & 31;

    // ---- stage input via cp.async: 4 warps x 10 (ci,row) pairs ----
    {
        const int xo = lane << 2;
        const float* xg = x + ((long long)b * 256 + head) * PLANE + xo;  // ci stride 64*PLANE
        uint32_t sa = (uint32_t)__cvta_generic_to_shared(s_in) + (uint32_t)(xo * 4);
        #pragma unroll
        for (int k = 0; k < 10; k++) {
            const int rr = wrp + (k << 2);            // 0..39
            const int ci = rr / SROWS;
            const int r  = rr - ci * SROWS;
            const int y  = y0 - 1 + r;
            const bool ok = (y >= 0) && (y < H);
            const int yc = ok ? y : 0;
            cpasync16(sa + (uint32_t)((ci * PLANE_P + r * SROW_P) * 4),
                      xg + ci * (64 * PLANE) + yc * W, ok);
        }
        asm volatile("cp.async.commit_group;\n");
    }

    // ---- stage weights as co-pair float2 + bias pairs ----
    if (tid < 72) {
        const int cp  = tid & 1;            // co pair: (2cp, 2cp+1)
        const int t9  = (tid >> 1) % 9;     // ky*3+kx
        const int ci  = (tid >> 1) / 9;
        const float w0 = w[((head * 4 + 2 * cp)     * 4 + ci) * 9 + t9];
        const float w1 = w[((head * 4 + 2 * cp + 1) * 4 + ci) * 9 + t9];
        s_w[(ci * 9 + t9) * 2 + cp] = pk(w0, w1);
    }
    if (tid < 2)
        s_b[tid] = pk(bias[head * 4 + 2 * tid], bias[head * 4 + 2 * tid + 1]);

    asm volatile("cp.async.wait_group 0;\n");
    __syncthreads();

    // ---- compute: warp = output rows (2*wrp, 2*wrp+1); thread = 4 px x 4 co x 2 rows ----
    u64 acc0[2][4], acc1[2][4];        // [row][q]; acc0=(co0,co1), acc1=(co2,co3)
    {
        const u64 b0 = s_b[0];
        const u64 b1 = s_b[1];
        #pragma unroll
        for (int rw = 0; rw < 2; rw++)
            #pragma unroll
            for (int q = 0; q < 4; q++) { acc0[rw][q] = b0; acc1[rw][q] = b1; }
    }

    const float* pl0 = s_in + (2 * wrp) * SROW_P + (lane << 2);
    const u64*   wci = s_w;

    #pragma unroll 1
    for (int ci = 0; ci < 4; ci++) {
        #pragma unroll
        for (int ky = 0; ky < 3; ky++) {
            // weight-set for this ky, shared by both output rows
            const ulonglong2* wp = (const ulonglong2*)(wci + ky * 6);
            const ulonglong2 wv0 = wp[0], wv1 = wp[1], wv2 = wp[2];

            #pragma unroll
            for (int rw = 0; rw < 2; rw++) {
                // input smem row = (2*wrp + rw) + ky
                float4 B = *(const float4*)(pl0 + (rw + ky) * SROW_P);

                float A = __shfl_up_sync(0xffffffffu, B.w, 1);
                float E = __shfl_down_sync(0xffffffffu, B.x, 1);
                if (lane == 0)  A = 0.0f;     // x = -1
                if (lane == 31) E = 0.0f;     // x = 128

                u64 dv[6];
                dv[0] = pk(A, A);
                dv[1] = pk(B.x, B.x);
                dv[2] = pk(B.y, B.y);
                dv[3] = pk(B.z, B.z);
                dv[4] = pk(B.w, B.w);
                dv[5] = pk(E, E);

                #pragma unroll
                for (int q = 0; q < 4; q++) {
                    ffma2(acc0[rw][q], wv0.x, dv[q]);
                    ffma2(acc1[rw][q], wv0.y, dv[q]);
                    ffma2(acc0[rw][q], wv1.x, dv[q + 1]);
                    ffma2(acc1[rw][q], wv1.y, dv[q + 1]);
                    ffma2(acc0[rw][q], wv2.x, dv[q + 2]);
                    ffma2(acc1[rw][q], wv2.y, dv[q + 2]);
                }
            }
        }
        pl0 += PLANE_P;
        wci += 18;
    }

    // ---- store: 2 rows x 4 co, STG.128 coalesced across the warp ----
    #pragma unroll
    for (int rw = 0; rw < 2; rw++) {
        const int y = y0 + 2 * wrp + rw;
        float* obase = out + (((long long)b * 256 + head) * H + y) * W + (lane << 2);
        float l0[4], h0[4], l1[4], h1[4];
        #pragma unroll
        for (int q = 0; q < 4; q++) {
            upk(acc0[rw][q], l0[q], h0[q]);
            upk(acc1[rw][q], l1[q], h1[q]);
        }
        *(float4*)(obase)                          = make_float4(l0[0], l0[1], l0[2], l0[3]);
        *(float4*)(obase + (long long) 64 * PLANE) = make_float4(h0[0], h0[1], h0[2], h0[3]);
        *(float4*)(obase + (long long)128 * PLANE) = make_float4(l1[0], l1[1], l1[2], l1[3]);
        *(float4*)(obase + (long long)192 * PLANE) = make_float4(h1[0], h1[1], h1[2], h1[3]);
    }
}

extern "C" void kernel_launch(void* const* d_in, const int* in_sizes, int n_in,
                              void* d_out, int out_size) {
    const float* x    = (const float*)d_in[0];
    const float* w    = (const float*)d_in[1];
    const float* bias = (const float*)d_in[2];
    float* out        = (float*)d_out;
    (void)in_sizes; (void)n_in; (void)out_size;
    cudaFuncSetAttribute(bdconv_kernel,
                         cudaFuncAttributeMaxDynamicSharedMemorySize, SMEM_BYTES);
    bdconv_kernel<<<32 * 64 * 16, THREADS, SMEM_BYTES>>>(x, w, bias, out);
}

// round 15
// speedup vs baseline: 1.0645x; 1.0645x over previous
#include <cuda_runtime.h>
#include <cstdint>

// Block-diagonal grouped conv2d: 64 groups, 4 in-ch -> 4 out-ch per group, 3x3, pad 1.
// x:   (32, 256, 128, 128) fp32, channel index = ci*64 + head
// w:   (64, 4, 4, 3, 3)          w[head][co][ci][ky][kx]
// b:   (64, 4)
// out: (32, 256, 128, 128) fp32, channel index = co*64 + head
//
// v15 = v12 (128-thr, TY=8, 8 CTAs/SM, cp.async staging, 2-row weight-
//       amortized co-pair f32x2 core) with shuffle/select edges replaced by
//       independent LDS.64 reads from pre-zeroed halo columns (flat 29-cyc
//       load latency, no serial SHFL chain, no SELs).

#define TY 8
#define SROWS (TY + 2)               // 10
#define SROW_P 136                   // cols: [0..1]pad [2..3]=x{-2,-1} [4..131]=x0..127 [132..133]=x{128,129}
#define PLANE_P (SROWS * SROW_P)     // 1360
#define S_IN_FLOATS (4 * PLANE_P)    // 5440
#define THREADS 128
#define H 128
#define W 128
#define PLANE (H * W)
// s_in + 72 weight u64 + 2 bias u64
#define SMEM_BYTES (S_IN_FLOATS * 4 + 74 * 8)

typedef unsigned long long u64;

__device__ __forceinline__ u64 pk(float lo, float hi) {
    u64 r; asm("mov.b64 %0, {%1, %2};" : "=l"(r) : "f"(lo), "f"(hi)); return r;
}
__device__ __forceinline__ void upk(u64 v, float &lo, float &hi) {
    asm("mov.b64 {%0, %1}, %2;" : "=f"(lo), "=f"(hi) : "l"(v));
}
// d += a*b  (packed 2x fp32)
__device__ __forceinline__ void ffma2(u64 &d, u64 a, u64 b) {
    asm("fma.rn.f32x2 %0, %1, %2, %0;" : "+l"(d) : "l"(a), "l"(b));
}
__device__ __forceinline__ void cpasync16(uint32_t saddr, const float* g, bool pred) {
    int sz = pred ? 16 : 0;
    asm volatile("cp.async.cg.shared.global [%0], [%1], 16, %2;\n"
                 :: "r"(saddr), "l"(g), "r"(sz));
}

__global__ __launch_bounds__(THREADS, 8)
void bdconv_kernel(const float* __restrict__ x, const float* __restrict__ w,
                   const float* __restrict__ bias, float* __restrict__ out) {
    extern __shared__ __align__(16) float smem[];
    float* s_in = smem;                          // [ci][r][col], col = x+4
    u64*   s_w  = (u64*)(smem + S_IN_FLOATS);    // [ci][ky][kx][cp] co-pair
    u64*   s_b  = s_w + 72;                      // [cp]

    const int blk  = blockIdx.x;
    const int tile = blk & 15;          // 16 row-tiles of 8
    const int head = (blk >> 4) & 63;
    const int b    = blk >> 10;
    const int y0   = tile * TY;
    const int tid  = threadIdx.x;
    const int wrp  = tid >> 5;
    const int lane = tid & 31;

    // ---- stage input via cp.async: 4 warps x 10 (ci,row) pairs; interior cols ----
    {
        const int xo = lane << 2;
        const float* xg = x + ((long long)b * 256 + head) * PLANE + xo;  // ci stride 64*PLANE
        uint32_t sa = (uint32_t)__cvta_generic_to_shared(s_in) + (uint32_t)((4 + xo) * 4);
        #pragma unroll
        for (int k = 0; k < 10; k++) {
            const int rr = wrp + (k << 2);            // 0..39
            const int ci = rr / SROWS;
            const int r  = rr - ci * SROWS;
            const int y  = y0 - 1 + r;
            const bool ok = (y >= 0) && (y < H);
            const int yc = ok ? y : 0;
            cpasync16(sa + (uint32_t)((ci * PLANE_P + r * SROW_P) * 4),
                      xg + ci * (64 * PLANE) + yc * W, ok);
        }
        asm volatile("cp.async.commit_group;\n");
    }

    // ---- zero halo columns: cols {2,3} (x=-2,-1) and {132,133} (x=128,129) ----
    for (int t = tid; t < 4 * SROWS * 4; t += THREADS) {   // 160 words
        const int row = t >> 2;                            // 0..39 = ci*10 + r
        const int c4  = t & 3;
        const int col = (c4 < 2) ? (2 + c4) : (130 + c4);  // 2,3,132,133
        s_in[row * SROW_P + col] = 0.0f;
    }

    // ---- stage weights as co-pair float2 + bias pairs ----
    if (tid < 72) {
        const int cp  = tid & 1;            // co pair: (2cp, 2cp+1)
        const int t9  = (tid >> 1) % 9;     // ky*3+kx
        const int ci  = (tid >> 1) / 9;
        const float w0 = w[((head * 4 + 2 * cp)     * 4 + ci) * 9 + t9];
        const float w1 = w[((head * 4 + 2 * cp + 1) * 4 + ci) * 9 + t9];
        s_w[(ci * 9 + t9) * 2 + cp] = pk(w0, w1);
    }
    if (tid < 2)
        s_b[tid] = pk(bias[head * 4 + 2 * tid], bias[head * 4 + 2 * tid + 1]);

    asm volatile("cp.async.wait_group 0;\n");
    __syncthreads();

    // ---- compute: warp = output rows (2*wrp, 2*wrp+1); thread = 4 px x 4 co x 2 rows ----
    u64 acc0[2][4], acc1[2][4];        // [row][q]; acc0=(co0,co1), acc1=(co2,co3)
    {
        const u64 b0 = s_b[0];
        const u64 b1 = s_b[1];
        #pragma unroll
        for (int rw = 0; rw < 2; rw++)
            #pragma unroll
            for (int q = 0; q < 4; q++) { acc0[rw][q] = b0; acc1[rw][q] = b1; }
    }

    // per-thread base: row 2*wrp, col of x=4*lane (interior col 4+4*lane)
    const float* pl0 = s_in + (2 * wrp) * SROW_P + (lane << 2);
    const u64*   wci = s_w;

    #pragma unroll 1
    for (int ci = 0; ci < 4; ci++) {
        #pragma unroll
        for (int ky = 0; ky < 3; ky++) {
            // weight-set for this ky, shared by both output rows
            const ulonglong2* wp = (const ulonglong2*)(wci + ky * 6);
            const ulonglong2 wv0 = wp[0], wv1 = wp[1], wv2 = wp[2];

            #pragma unroll
            for (int rw = 0; rw < 2; rw++) {
                // input smem row = (2*wrp + rw) + ky
                const float* rp = pl0 + (rw + ky) * SROW_P;
                float4 B = *(const float4*)(rp + 4);   // x = 4l .. 4l+3
                float2 L = *(const float2*)(rp + 2);   // {x-2, x-1}
                float2 R = *(const float2*)(rp + 8);   // {x+4, x+5}

                u64 dv[6];
                dv[0] = pk(L.y, L.y);   // x = 4l-1
                dv[1] = pk(B.x, B.x);
                dv[2] = pk(B.y, B.y);
                dv[3] = pk(B.z, B.z);
                dv[4] = pk(B.w, B.w);
                dv[5] = pk(R.x, R.x);   // x = 4l+4

                #pragma unroll
                for (int q = 0; q < 4; q++) {
                    ffma2(acc0[rw][q], wv0.x, dv[q]);
                    ffma2(acc1[rw][q], wv0.y, dv[q]);
                    ffma2(acc0[rw][q], wv1.x, dv[q + 1]);
                    ffma2(acc1[rw][q], wv1.y, dv[q + 1]);
                    ffma2(acc0[rw][q], wv2.x, dv[q + 2]);
                    ffma2(acc1[rw][q], wv2.y, dv[q + 2]);
                }
            }
        }
        pl0 += PLANE_P;
        wci += 18;
    }

    // ---- store: 2 rows x 4 co, STG.128 coalesced across the warp ----
    #pragma unroll
    for (int rw = 0; rw < 2; rw++) {
        const int y = y0 + 2 * wrp + rw;
        float* obase = out + (((long long)b * 256 + head) * H + y) * W + (lane << 2);
        float l0[4], h0[4], l1[4], h1[4];
        #pragma unroll
        for (int q = 0; q < 4; q++) {
            upk(acc0[rw][q], l0[q], h0[q]);
            upk(acc1[rw][q], l1[q], h1[q]);
        }
        *(float4*)(obase)                          = make_float4(l0[0], l0[1], l0[2], l0[3]);
        *(float4*)(obase + (long long) 64 * PLANE) = make_float4(h0[0], h0[1], h0[2], h0[3]);
        *(float4*)(obase + (long long)128 * PLANE) = make_float4(l1[0], l1[1], l1[2], l1[3]);
        *(float4*)(obase + (long long)192 * PLANE) = make_float4(h1[0], h1[1], h1[2], h1[3]);
    }
}

extern "C" void kernel_launch(void* const* d_in, const int* in_sizes, int n_in,
                              void* d_out, int out_size) {
    const float* x    = (const float*)d_in[0];
    const float* w    = (const float*)d_in[1];
    const float* bias = (const float*)d_in[2];
    float* out        = (float*)d_out;
    (void)in_sizes; (void)n_in; (void)out_size;
    cudaFuncSetAttribute(bdconv_kernel,
                         cudaFuncAttributeMaxDynamicSharedMemorySize, SMEM_BYTES);
    bdconv_kernel<<<32 * 64 * 16, THREADS, SMEM_BYTES>>>(x, w, bias, out);
}

// round 16
// speedup vs baseline: 1.0765x; 1.0113x over previous
#include <cuda_runtime.h>
#include <cstdint>

// Block-diagonal grouped conv2d: 64 groups, 4 in-ch -> 4 out-ch per group, 3x3, pad 1.
// x:   (32, 256, 128, 128) fp32, channel index = ci*64 + head
// w:   (64, 4, 4, 3, 3)          w[head][co][ci][ky][kx]
// b:   (64, 4)
// out: (32, 256, 128, 128) fp32, channel index = co*64 + head
//
// v16 = v12 (128-thr, TY=8, 8 CTAs/SM, 2-row weight-amortized co-pair f32x2
//       core, shuffle edges) + split-ci cp.async pipeline: stage ci{0,1} and
//       ci{2,3} as separate groups; compute ci0-1 overlaps the DRAM time of
//       ci2-3.

#define TY 8
#define SROWS (TY + 2)               // 10
#define SROW_P 132                   // row stride (floats); only 128 used
#define PLANE_P (SROWS * SROW_P)     // 1320
#define S_IN_FLOATS (4 * PLANE_P)    // 5280
#define THREADS 128
#define H 128
#define W 128
#define PLANE (H * W)
// s_in + 72 weight u64 + 2 bias u64
#define SMEM_BYTES (S_IN_FLOATS * 4 + 74 * 8)

typedef unsigned long long u64;

__device__ __forceinline__ u64 pk(float lo, float hi) {
    u64 r; asm("mov.b64 %0, {%1, %2};" : "=l"(r) : "f"(lo), "f"(hi)); return r;
}
__device__ __forceinline__ void upk(u64 v, float &lo, float &hi) {
    asm("mov.b64 {%0, %1}, %2;" : "=f"(lo), "=f"(hi) : "l"(v));
}
// d += a*b  (packed 2x fp32)
__device__ __forceinline__ void ffma2(u64 &d, u64 a, u64 b) {
    asm("fma.rn.f32x2 %0, %1, %2, %0;" : "+l"(d) : "l"(a), "l"(b));
}
__device__ __forceinline__ void cpasync16(uint32_t saddr, const float* g, bool pred) {
    int sz = pred ? 16 : 0;
    asm volatile("cp.async.cg.shared.global [%0], [%1], 16, %2;\n"
                 :: "r"(saddr), "l"(g), "r"(sz));
}

__global__ __launch_bounds__(THREADS, 8)
void bdconv_kernel(const float* __restrict__ x, const float* __restrict__ w,
                   const float* __restrict__ bias, float* __restrict__ out) {
    extern __shared__ __align__(16) float smem[];
    float* s_in = smem;                          // [ci][r][col], row-major
    u64*   s_w  = (u64*)(smem + S_IN_FLOATS);    // [ci][ky][kx][cp] co-pair
    u64*   s_b  = s_w + 72;                      // [cp]

    const int blk  = blockIdx.x;
    const int tile = blk & 15;          // 16 row-tiles of 8
    const int head = (blk >> 4) & 63;
    const int b    = blk >> 10;
    const int y0   = tile * TY;
    const int tid  = threadIdx.x;
    const int wrp  = tid >> 5;
    const int lane = tid & 31;

    // ---- stage input via cp.async in TWO groups: ci{0,1} then ci{2,3} ----
    {
        const int xo = lane << 2;
        const float* xg = x + ((long long)b * 256 + head) * PLANE + xo;  // ci stride 64*PLANE
        uint32_t sa = (uint32_t)__cvta_generic_to_shared(s_in) + (uint32_t)(xo * 4);
        // group A: rows rr = 0..19 (ci 0,1)
        #pragma unroll
        for (int k = 0; k < 5; k++) {
            const int rr = wrp + (k << 2);            // 0..19
            const int ci = rr / SROWS;
            const int r  = rr - ci * SROWS;
            const int y  = y0 - 1 + r;
            const bool ok = (y >= 0) && (y < H);
            const int yc = ok ? y : 0;
            cpasync16(sa + (uint32_t)((ci * PLANE_P + r * SROW_P) * 4),
                      xg + ci * (64 * PLANE) + yc * W, ok);
        }
        asm volatile("cp.async.commit_group;\n");
        // group B: rows rr = 20..39 (ci 2,3)
        #pragma unroll
        for (int k = 5; k < 10; k++) {
            const int rr = wrp + (k << 2);            // 20..39
            const int ci = rr / SROWS;
            const int r  = rr - ci * SROWS;
            const int y  = y0 - 1 + r;
            const bool ok = (y >= 0) && (y < H);
            const int yc = ok ? y : 0;
            cpasync16(sa + (uint32_t)((ci * PLANE_P + r * SROW_P) * 4),
                      xg + ci * (64 * PLANE) + yc * W, ok);
        }
        asm volatile("cp.async.commit_group;\n");
    }

    // ---- stage weights as co-pair float2 + bias pairs ----
    if (tid < 72) {
        const int cp  = tid & 1;            // co pair: (2cp, 2cp+1)
        const int t9  = (tid >> 1) % 9;     // ky*3+kx
        const int ci  = (tid >> 1) / 9;
        const float w0 = w[((head * 4 + 2 * cp)     * 4 + ci) * 9 + t9];
        const float w1 = w[((head * 4 + 2 * cp + 1) * 4 + ci) * 9 + t9];
        s_w[(ci * 9 + t9) * 2 + cp] = pk(w0, w1);
    }
    if (tid < 2)
        s_b[tid] = pk(bias[head * 4 + 2 * tid], bias[head * 4 + 2 * tid + 1]);

    // ---- compute: warp = output rows (2*wrp, 2*wrp+1); thread = 4 px x 4 co x 2 rows ----
    u64 acc0[2][4], acc1[2][4];        // [row][q]; acc0=(co0,co1), acc1=(co2,co3)

    const float* pl0 = s_in + (2 * wrp) * SROW_P + (lane << 2);
    const u64*   wci = s_w;

    // phase 0: wait for group A (1 group still pending), compute ci 0-1
    asm volatile("cp.async.wait_group 1;\n");
    __syncthreads();
    {
        const u64 b0 = s_b[0];
        const u64 b1 = s_b[1];
        #pragma unroll
        for (int rw = 0; rw < 2; rw++)
            #pragma unroll
            for (int q = 0; q < 4; q++) { acc0[rw][q] = b0; acc1[rw][q] = b1; }
    }

    #pragma unroll 1
    for (int phase = 0; phase < 2; phase++) {
        #pragma unroll 1
        for (int cc = 0; cc < 2; cc++) {
            #pragma unroll
            for (int ky = 0; ky < 3; ky++) {
                // weight-set for this ky, shared by both output rows
                const ulonglong2* wp = (const ulonglong2*)(wci + ky * 6);
                const ulonglong2 wv0 = wp[0], wv1 = wp[1], wv2 = wp[2];

                #pragma unroll
                for (int rw = 0; rw < 2; rw++) {
                    // input smem row = (2*wrp + rw) + ky
                    float4 B = *(const float4*)(pl0 + (rw + ky) * SROW_P);

                    float A = __shfl_up_sync(0xffffffffu, B.w, 1);
                    float E = __shfl_down_sync(0xffffffffu, B.x, 1);
                    if (lane == 0)  A = 0.0f;     // x = -1
                    if (lane == 31) E = 0.0f;     // x = 128

                    u64 dv[6];
                    dv[0] = pk(A, A);
                    dv[1] = pk(B.x, B.x);
                    dv[2] = pk(B.y, B.y);
                    dv[3] = pk(B.z, B.z);
                    dv[4] = pk(B.w, B.w);
                    dv[5] = pk(E, E);

                    #pragma unroll
                    for (int q = 0; q < 4; q++) {
                        ffma2(acc0[rw][q], wv0.x, dv[q]);
                        ffma2(acc1[rw][q], wv0.y, dv[q]);
                        ffma2(acc0[rw][q], wv1.x, dv[q + 1]);
                        ffma2(acc1[rw][q], wv1.y, dv[q + 1]);
                        ffma2(acc0[rw][q], wv2.x, dv[q + 2]);
                        ffma2(acc1[rw][q], wv2.y, dv[q + 2]);
                    }
                }
            }
            pl0 += PLANE_P;
            wci += 18;
        }
        if (phase == 0) {
            // group B (ci 2-3) must be fully landed before reading
            asm volatile("cp.async.wait_group 0;\n");
            __syncthreads();
        }
    }

    // ---- store: 2 rows x 4 co, STG.128 coalesced across the warp ----
    #pragma unroll
    for (int rw = 0; rw < 2; rw++) {
        const int y = y0 + 2 * wrp + rw;
        float* obase = out + (((long long)b * 256 + head) * H + y) * W + (lane << 2);
        float l0[4], h0[4], l1[4], h1[4];
        #pragma unroll
        for (int q = 0; q < 4; q++) {
            upk(acc0[rw][q], l0[q], h0[q]);
            upk(acc1[rw][q], l1[q], h1[q]);
        }
        *(float4*)(obase)                          = make_float4(l0[0], l0[1], l0[2], l0[3]);
        *(float4*)(obase + (long long) 64 * PLANE) = make_float4(h0[0], h0[1], h0[2], h0[3]);
        *(float4*)(obase + (long long)128 * PLANE) = make_float4(l1[0], l1[1], l1[2], l1[3]);
        *(float4*)(obase + (long long)192 * PLANE) = make_float4(h1[0], h1[1], h1[2], h1[3]);
    }
}

extern "C" void kernel_launch(void* const* d_in, const int* in_sizes, int n_in,
                              void* d_out, int out_size) {
    const float* x    = (const float*)d_in[0];
    const float* w    = (const float*)d_in[1];
    const float* bias = (const float*)d_in[2];
    float* out        = (float*)d_out;
    (void)in_sizes; (void)n_in; (void)out_size;
    cudaFuncSetAttribute(bdconv_kernel,
                         cudaFuncAttributeMaxDynamicSharedMemorySize, SMEM_BYTES);
    bdconv_kernel<<<32 * 64 * 16, THREADS, SMEM_BYTES>>>(x, w, bias, out);
}